// round 5
// baseline (speedup 1.0000x reference)
#include <cuda_runtime.h>
#include <math.h>
#include <stdint.h>

// Problem dims
#define BB 2
#define SSEQ 2048
#define EE 1024
#define HH 16
#define DD 64
#define MMROWS (BB * SSEQ)  // 4096

// Scratch (device globals: allocation-free)
__device__ float g_Q[BB * HH * SSEQ * DD];
__device__ float g_K[BB * HH * SSEQ * DD];
__device__ float g_V[BB * HH * SSEQ * DD];
__device__ float g_attn[BB * SSEQ * EE];

// ---------------------------------------------------------------------------
// helpers
// ---------------------------------------------------------------------------
__device__ __forceinline__ float f2tf(float x) {
    uint32_t r;
    asm("cvt.rna.tf32.f32 %0, %1;" : "=r"(r) : "f"(x));
    return __uint_as_float(r);
}

__device__ __forceinline__ void mma_tf32(float& c0, float& c1, float& c2, float& c3,
                                         uint32_t a0, uint32_t a1, uint32_t a2, uint32_t a3,
                                         uint32_t b0, uint32_t b1) {
    asm volatile(
        "mma.sync.aligned.m16n8k8.row.col.f32.tf32.tf32.f32 "
        "{%0,%1,%2,%3}, {%4,%5,%6,%7}, {%8,%9}, {%0,%1,%2,%3};\n"
        : "+f"(c0), "+f"(c1), "+f"(c2), "+f"(c3)
        : "r"(a0), "r"(a1), "r"(a2), "r"(a3), "r"(b0), "r"(b1));
}

__device__ __forceinline__ void cpa16(uint32_t dst, const void* src) {
    asm volatile("cp.async.cg.shared.global [%0], [%1], 16;\n" :: "r"(dst), "l"(src));
}
__device__ __forceinline__ void cpa_commit() {
    asm volatile("cp.async.commit_group;\n");
}
__device__ __forceinline__ void cpa_wait_all() {
    asm volatile("cp.async.wait_group 0;\n");
}

// ---------------------------------------------------------------------------
// Fused QKV GEMM (grid.z selects Q/K/V) with RoPE fused into the epilogue for
// Q and K. C = A @ W^T + bias, then (z<2) rope, then tf32-round, scatter to
// [B,H,S,D]. Row-major smem tiles [128][20], register double-buffered.
// 256 thr = 8 warps (2m x 4n), CTA tile 128x128, BK=16.
// ---------------------------------------------------------------------------
#define GPD 20

__global__ __launch_bounds__(256) void gemm_qkv(
    const float* __restrict__ q_in, const float* __restrict__ k_in,
    const float* __restrict__ v_in,
    const float* __restrict__ Wq, const float* __restrict__ bq,
    const float* __restrict__ Wk, const float* __restrict__ bk,
    const float* __restrict__ Wv, const float* __restrict__ bv) {
    const int z = blockIdx.z;
    const float* A = (z == 0) ? q_in : (z == 1) ? k_in : v_in;
    const float* W = (z == 0) ? Wq : (z == 1) ? Wk : Wv;
    const float* bias = (z == 0) ? bq : (z == 1) ? bk : bv;
    float* dst = (z == 0) ? g_Q : (z == 1) ? g_K : g_V;

    __shared__ __align__(16) float As[2][128][GPD];
    __shared__ __align__(16) float Bs[2][128][GPD];
    __shared__ float invf[32];

    const int tid = threadIdx.x;
    const int n0 = blockIdx.x * 128;
    const int m0 = blockIdx.y * 128;
    const int wid = tid >> 5;
    const int lane = tid & 31;
    const int g = lane >> 2;
    const int t4 = lane & 3;
    const int mw = (wid & 1) * 64;
    const int nw = (wid >> 1) * 32;

    const int sm = tid >> 2;
    const int skq = (tid & 3) * 4;

    if (tid < 32)
        invf[tid] = (float)exp(-(double)tid * (9.210340371976184 / 32.0));

    float acc[4][4][4];
#pragma unroll
    for (int mt = 0; mt < 4; mt++)
#pragma unroll
        for (int nt = 0; nt < 4; nt++)
#pragma unroll
            for (int qq = 0; qq < 4; qq++) acc[mt][nt][qq] = 0.f;

    const int nsteps = EE / 16;  // 64

    {
        float4 va0 = *(const float4*)&A[(size_t)(m0 + sm) * EE + skq];
        float4 va1 = *(const float4*)&A[(size_t)(m0 + sm + 64) * EE + skq];
        float4 vw0 = *(const float4*)&W[(size_t)(n0 + sm) * EE + skq];
        float4 vw1 = *(const float4*)&W[(size_t)(n0 + sm + 64) * EE + skq];
        *(float4*)&As[0][sm][skq]      = make_float4(f2tf(va0.x), f2tf(va0.y), f2tf(va0.z), f2tf(va0.w));
        *(float4*)&As[0][sm + 64][skq] = make_float4(f2tf(va1.x), f2tf(va1.y), f2tf(va1.z), f2tf(va1.w));
        *(float4*)&Bs[0][sm][skq]      = make_float4(f2tf(vw0.x), f2tf(vw0.y), f2tf(vw0.z), f2tf(vw0.w));
        *(float4*)&Bs[0][sm + 64][skq] = make_float4(f2tf(vw1.x), f2tf(vw1.y), f2tf(vw1.z), f2tf(vw1.w));
    }
    __syncthreads();

    for (int s = 0; s < nsteps; s++) {
        const int cur = s & 1;
        float4 va0, va1, vw0, vw1;
        const bool more = (s + 1 < nsteps);
        if (more) {
            int k0 = (s + 1) * 16;
            va0 = *(const float4*)&A[(size_t)(m0 + sm) * EE + k0 + skq];
            va1 = *(const float4*)&A[(size_t)(m0 + sm + 64) * EE + k0 + skq];
            vw0 = *(const float4*)&W[(size_t)(n0 + sm) * EE + k0 + skq];
            vw1 = *(const float4*)&W[(size_t)(n0 + sm + 64) * EE + k0 + skq];
        }

#pragma unroll
        for (int kk = 0; kk < 16; kk += 8) {
            uint32_t af[4][4];
#pragma unroll
            for (int mt = 0; mt < 4; mt++) {
                int m = mw + mt * 16 + g;
                af[mt][0] = __float_as_uint(As[cur][m][kk + t4]);
                af[mt][1] = __float_as_uint(As[cur][m + 8][kk + t4]);
                af[mt][2] = __float_as_uint(As[cur][m][kk + t4 + 4]);
                af[mt][3] = __float_as_uint(As[cur][m + 8][kk + t4 + 4]);
            }
            uint32_t bf[4][2];
#pragma unroll
            for (int nt = 0; nt < 4; nt++) {
                int n = nw + nt * 8 + g;
                bf[nt][0] = __float_as_uint(Bs[cur][n][kk + t4]);
                bf[nt][1] = __float_as_uint(Bs[cur][n][kk + t4 + 4]);
            }
#pragma unroll
            for (int mt = 0; mt < 4; mt++)
#pragma unroll
                for (int nt = 0; nt < 4; nt++)
                    mma_tf32(acc[mt][nt][0], acc[mt][nt][1], acc[mt][nt][2], acc[mt][nt][3],
                             af[mt][0], af[mt][1], af[mt][2], af[mt][3],
                             bf[nt][0], bf[nt][1]);
        }

        if (more) {
            const int nxt = cur ^ 1;
            *(float4*)&As[nxt][sm][skq]      = make_float4(f2tf(va0.x), f2tf(va0.y), f2tf(va0.z), f2tf(va0.w));
            *(float4*)&As[nxt][sm + 64][skq] = make_float4(f2tf(va1.x), f2tf(va1.y), f2tf(va1.z), f2tf(va1.w));
            *(float4*)&Bs[nxt][sm][skq]      = make_float4(f2tf(vw0.x), f2tf(vw0.y), f2tf(vw0.z), f2tf(vw0.w));
            *(float4*)&Bs[nxt][sm + 64][skq] = make_float4(f2tf(vw1.x), f2tf(vw1.y), f2tf(vw1.z), f2tf(vw1.w));
            __syncthreads();
        }
    }

    // Epilogue: fragment cols (gn, gn+1) with gn even == RoPE pair (2p, 2p+1).
#pragma unroll
    for (int mt = 0; mt < 4; mt++) {
        int gm0 = m0 + mw + mt * 16 + g;
        int gm1 = gm0 + 8;
        int s0 = gm0 & (SSEQ - 1), s1 = gm1 & (SSEQ - 1);
        int bb0 = gm0 >> 11, bb1 = gm1 >> 11;
#pragma unroll
        for (int nt = 0; nt < 4; nt++) {
            int gn = n0 + nw + nt * 8 + 2 * t4;
            int h = gn >> 6, d0 = gn & 63;
            float bv0 = bias[gn], bv1 = bias[gn + 1];
            float e00 = acc[mt][nt][0] + bv0, e01 = acc[mt][nt][1] + bv1;
            float e10 = acc[mt][nt][2] + bv0, e11 = acc[mt][nt][3] + bv1;
            if (z < 2) {  // RoPE on Q, K (same math order as the old rope kernel)
                float if0 = invf[d0 & 31], if1 = invf[(d0 + 1) & 31];
                float sa, ca, sb, cb;
                sincosf((float)s0 * if0, &sa, &ca);
                sincosf((float)s0 * if1, &sb, &cb);
                float y00 = e00 * ca - e01 * sa;
                float y01 = e01 * cb + e00 * sb;
                sincosf((float)s1 * if0, &sa, &ca);
                sincosf((float)s1 * if1, &sb, &cb);
                float y10 = e10 * ca - e11 * sa;
                float y11 = e11 * cb + e10 * sb;
                e00 = y00; e01 = y01; e10 = y10; e11 = y11;
            }
            // producer-side tf32 rounding for all of Q,K,V
            e00 = f2tf(e00); e01 = f2tf(e01); e10 = f2tf(e10); e11 = f2tf(e11);
            *(float2*)&dst[(((size_t)(bb0 * HH + h)) * SSEQ + s0) * DD + d0] = make_float2(e00, e01);
            *(float2*)&dst[(((size_t)(bb1 * HH + h)) * SSEQ + s1) * DD + d0] = make_float2(e10, e11);
        }
    }
}

// ---------------------------------------------------------------------------
// Output GEMM: out = g_attn @ Wo^T + bo  (row-major out)
// ---------------------------------------------------------------------------
__global__ __launch_bounds__(256) void gemm_out(const float* __restrict__ W,
                                                const float* __restrict__ bias,
                                                float* __restrict__ Cout) {
    const float* A = g_attn;

    __shared__ __align__(16) float As[2][128][GPD];
    __shared__ __align__(16) float Bs[2][128][GPD];

    const int tid = threadIdx.x;
    const int n0 = blockIdx.x * 128;
    const int m0 = blockIdx.y * 128;
    const int wid = tid >> 5;
    const int lane = tid & 31;
    const int g = lane >> 2;
    const int t4 = lane & 3;
    const int mw = (wid & 1) * 64;
    const int nw = (wid >> 1) * 32;
    const int sm = tid >> 2;
    const int skq = (tid & 3) * 4;

    float acc[4][4][4];
#pragma unroll
    for (int mt = 0; mt < 4; mt++)
#pragma unroll
        for (int nt = 0; nt < 4; nt++)
#pragma unroll
            for (int qq = 0; qq < 4; qq++) acc[mt][nt][qq] = 0.f;

    const int nsteps = EE / 16;

    {
        float4 va0 = *(const float4*)&A[(size_t)(m0 + sm) * EE + skq];
        float4 va1 = *(const float4*)&A[(size_t)(m0 + sm + 64) * EE + skq];
        float4 vw0 = *(const float4*)&W[(size_t)(n0 + sm) * EE + skq];
        float4 vw1 = *(const float4*)&W[(size_t)(n0 + sm + 64) * EE + skq];
        *(float4*)&As[0][sm][skq]      = make_float4(f2tf(va0.x), f2tf(va0.y), f2tf(va0.z), f2tf(va0.w));
        *(float4*)&As[0][sm + 64][skq] = make_float4(f2tf(va1.x), f2tf(va1.y), f2tf(va1.z), f2tf(va1.w));
        *(float4*)&Bs[0][sm][skq]      = make_float4(f2tf(vw0.x), f2tf(vw0.y), f2tf(vw0.z), f2tf(vw0.w));
        *(float4*)&Bs[0][sm + 64][skq] = make_float4(f2tf(vw1.x), f2tf(vw1.y), f2tf(vw1.z), f2tf(vw1.w));
    }
    __syncthreads();

    for (int s = 0; s < nsteps; s++) {
        const int cur = s & 1;
        float4 va0, va1, vw0, vw1;
        const bool more = (s + 1 < nsteps);
        if (more) {
            int k0 = (s + 1) * 16;
            va0 = *(const float4*)&A[(size_t)(m0 + sm) * EE + k0 + skq];
            va1 = *(const float4*)&A[(size_t)(m0 + sm + 64) * EE + k0 + skq];
            vw0 = *(const float4*)&W[(size_t)(n0 + sm) * EE + k0 + skq];
            vw1 = *(const float4*)&W[(size_t)(n0 + sm + 64) * EE + k0 + skq];
        }

#pragma unroll
        for (int kk = 0; kk < 16; kk += 8) {
            uint32_t af[4][4];
#pragma unroll
            for (int mt = 0; mt < 4; mt++) {
                int m = mw + mt * 16 + g;
                af[mt][0] = __float_as_uint(As[cur][m][kk + t4]);
                af[mt][1] = __float_as_uint(As[cur][m + 8][kk + t4]);
                af[mt][2] = __float_as_uint(As[cur][m][kk + t4 + 4]);
                af[mt][3] = __float_as_uint(As[cur][m + 8][kk + t4 + 4]);
            }
            uint32_t bf[4][2];
#pragma unroll
            for (int nt = 0; nt < 4; nt++) {
                int n = nw + nt * 8 + g;
                bf[nt][0] = __float_as_uint(Bs[cur][n][kk + t4]);
                bf[nt][1] = __float_as_uint(Bs[cur][n][kk + t4 + 4]);
            }
#pragma unroll
            for (int mt = 0; mt < 4; mt++)
#pragma unroll
                for (int nt = 0; nt < 4; nt++)
                    mma_tf32(acc[mt][nt][0], acc[mt][nt][1], acc[mt][nt][2], acc[mt][nt][3],
                             af[mt][0], af[mt][1], af[mt][2], af[mt][3],
                             bf[nt][0], bf[nt][1]);
        }

        if (more) {
            const int nxt = cur ^ 1;
            *(float4*)&As[nxt][sm][skq]      = make_float4(f2tf(va0.x), f2tf(va0.y), f2tf(va0.z), f2tf(va0.w));
            *(float4*)&As[nxt][sm + 64][skq] = make_float4(f2tf(va1.x), f2tf(va1.y), f2tf(va1.z), f2tf(va1.w));
            *(float4*)&Bs[nxt][sm][skq]      = make_float4(f2tf(vw0.x), f2tf(vw0.y), f2tf(vw0.z), f2tf(vw0.w));
            *(float4*)&Bs[nxt][sm + 64][skq] = make_float4(f2tf(vw1.x), f2tf(vw1.y), f2tf(vw1.z), f2tf(vw1.w));
            __syncthreads();
        }
    }

#pragma unroll
    for (int mt = 0; mt < 4; mt++) {
        int gm0 = m0 + mw + mt * 16 + g;
        int gm1 = gm0 + 8;
#pragma unroll
        for (int nt = 0; nt < 4; nt++) {
            int gn = n0 + nw + nt * 8 + 2 * t4;
            float bv0 = bias[gn], bv1 = bias[gn + 1];
            *(float2*)&Cout[(size_t)gm0 * EE + gn] = make_float2(acc[mt][nt][0] + bv0, acc[mt][nt][1] + bv1);
            *(float2*)&Cout[(size_t)gm1 * EE + gn] = make_float2(acc[mt][nt][2] + bv0, acc[mt][nt][3] + bv1);
        }
    }
}

// ---------------------------------------------------------------------------
// Flash attention, tf32 mma, cp.async double-buffered K/V.
// CTA = 256 thr (8 warps x 16 q-rows = 128 q-rows), K tile 64. stride 68.
// ---------------------------------------------------------------------------
#define ALD 68
#define QTT 128
#define NTILE (SSEQ / 64)  // 32

__global__ __launch_bounds__(256) void attn_tc(const int* __restrict__ mask) {
    extern __shared__ __align__(16) float smx[];
    float* Kb[2] = {smx, smx + 64 * ALD};
    float* Vb[2] = {smx + 2 * 64 * ALD, smx + 3 * 64 * ALD};
    float* Ss = smx + 4 * 64 * ALD;                 // [128][68]
    int* msk = (int*)(smx + 4 * 64 * ALD + QTT * ALD);  // [2][64]

    const int tid = threadIdx.x;
    const int wid = tid >> 5;
    const int lane = tid & 31;
    const int g = lane >> 2;
    const int t4 = lane & 3;
    const int qw = wid * 16;

    const int bh = blockIdx.y;
    const int q0 = blockIdx.x * QTT;
    const int b = bh / HH;
    const int h = bh - b * HH;
    const size_t base = (size_t)bh * SSEQ * DD;

    const uint32_t smem_u32 = (uint32_t)__cvta_generic_to_shared(smx);
    const uint32_t kb_u32[2] = {smem_u32, smem_u32 + 64 * ALD * 4};
    const uint32_t vb_u32[2] = {smem_u32 + 2 * 64 * ALD * 4, smem_u32 + 3 * 64 * ALD * 4};
    const uint32_t msk_u32 = smem_u32 + (4 * 64 * ALD + QTT * ALD) * 4;

    // Q fragments (loop-invariant, pre-rounded tf32)
    uint32_t aq[8][4];
    {
        const float* qr0 = &g_Q[base + (size_t)(q0 + qw + g) * DD];
        const float* qr1 = qr0 + 8 * DD;
#pragma unroll
        for (int kk8 = 0; kk8 < 8; kk8++) {
            aq[kk8][0] = __float_as_uint(qr0[kk8 * 8 + t4]);
            aq[kk8][1] = __float_as_uint(qr1[kk8 * 8 + t4]);
            aq[kk8][2] = __float_as_uint(qr0[kk8 * 8 + t4 + 4]);
            aq[kk8][3] = __float_as_uint(qr1[kk8 * 8 + t4 + 4]);
        }
    }

    float o[8][4];
#pragma unroll
    for (int nt = 0; nt < 8; nt++)
#pragma unroll
        for (int qq = 0; qq < 4; qq++) o[nt][qq] = 0.f;
    float mr0 = -INFINITY, mr1 = -INFINITY, lr0 = 0.f, lr1 = 0.f;

    // prefetch tile 0 (64x64 per tensor = 1024 float4; 256 thr -> 4 each)
    {
#pragma unroll
        for (int u = 0; u < 4; u++) {
            int n = tid + 256 * u;
            int r = n >> 4, c = (n & 15) * 4;
            cpa16(kb_u32[0] + (r * ALD + c) * 4, &g_K[base + (size_t)r * DD + c]);
            cpa16(vb_u32[0] + (r * ALD + c) * 4, &g_V[base + (size_t)r * DD + c]);
        }
        if (tid < 16) cpa16(msk_u32 + tid * 16, &mask[b * SSEQ + tid * 4]);
        cpa_commit();
    }

    for (int kt = 0; kt < NTILE; kt++) {
        cpa_wait_all();
        __syncthreads();

        const int cur = kt & 1;
        if (kt + 1 < NTILE) {
            const int k0 = (kt + 1) * 64;
            const int nb = cur ^ 1;
#pragma unroll
            for (int u = 0; u < 4; u++) {
                int n = tid + 256 * u;
                int r = n >> 4, c = (n & 15) * 4;
                cpa16(kb_u32[nb] + (r * ALD + c) * 4, &g_K[base + (size_t)(k0 + r) * DD + c]);
                cpa16(vb_u32[nb] + (r * ALD + c) * 4, &g_V[base + (size_t)(k0 + r) * DD + c]);
            }
            if (tid < 16) cpa16(msk_u32 + 256 * nb + tid * 16, &mask[b * SSEQ + k0 + tid * 4]);
            cpa_commit();
        }

        const float* Kc = Kb[cur];
        const float* Vc = Vb[cur];
        const int* mc = msk + 64 * cur;

        // S = Q @ K^T
        float s[8][4];
#pragma unroll
        for (int nt = 0; nt < 8; nt++)
#pragma unroll
            for (int qq = 0; qq < 4; qq++) s[nt][qq] = 0.f;
#pragma unroll
        for (int kk8 = 0; kk8 < 8; kk8++) {
            int kk = kk8 * 8;
#pragma unroll
            for (int nt = 0; nt < 8; nt++) {
                uint32_t b0 = __float_as_uint(Kc[(nt * 8 + g) * ALD + kk + t4]);
                uint32_t b1 = __float_as_uint(Kc[(nt * 8 + g) * ALD + kk + t4 + 4]);
                mma_tf32(s[nt][0], s[nt][1], s[nt][2], s[nt][3],
                         aq[kk8][0], aq[kk8][1], aq[kk8][2], aq[kk8][3], b0, b1);
            }
        }

        // scale + mask
#pragma unroll
        for (int nt = 0; nt < 8; nt++) {
            int mka = mc[nt * 8 + 2 * t4];
            int mkb = mc[nt * 8 + 2 * t4 + 1];
            s[nt][0] = mka ? s[nt][0] * 0.125f : -1e30f;
            s[nt][1] = mkb ? s[nt][1] * 0.125f : -1e30f;
            s[nt][2] = mka ? s[nt][2] * 0.125f : -1e30f;
            s[nt][3] = mkb ? s[nt][3] * 0.125f : -1e30f;
        }

        // online softmax (rows g / g+8; reduce over 4-lane group)
        float m0 = -INFINITY, m1 = -INFINITY;
#pragma unroll
        for (int nt = 0; nt < 8; nt++) {
            m0 = fmaxf(m0, fmaxf(s[nt][0], s[nt][1]));
            m1 = fmaxf(m1, fmaxf(s[nt][2], s[nt][3]));
        }
#pragma unroll
        for (int off = 1; off <= 2; off <<= 1) {
            m0 = fmaxf(m0, __shfl_xor_sync(0xffffffffu, m0, off));
            m1 = fmaxf(m1, __shfl_xor_sync(0xffffffffu, m1, off));
        }
        float mn0 = fmaxf(mr0, m0), mn1 = fmaxf(mr1, m1);
        float al0 = __expf(mr0 - mn0), al1 = __expf(mr1 - mn1);
        float ls0 = 0.f, ls1 = 0.f;
#pragma unroll
        for (int nt = 0; nt < 8; nt++) {
            s[nt][0] = __expf(s[nt][0] - mn0);
            s[nt][1] = __expf(s[nt][1] - mn0);
            s[nt][2] = __expf(s[nt][2] - mn1);
            s[nt][3] = __expf(s[nt][3] - mn1);
            ls0 += s[nt][0] + s[nt][1];
            ls1 += s[nt][2] + s[nt][3];
        }
#pragma unroll
        for (int off = 1; off <= 2; off <<= 1) {
            ls0 += __shfl_xor_sync(0xffffffffu, ls0, off);
            ls1 += __shfl_xor_sync(0xffffffffu, ls1, off);
        }
        mr0 = mn0; mr1 = mn1;
        lr0 = lr0 * al0 + ls0;
        lr1 = lr1 * al1 + ls1;
#pragma unroll
        for (int nt = 0; nt < 8; nt++) {
            o[nt][0] *= al0; o[nt][1] *= al0;
            o[nt][2] *= al1; o[nt][3] *= al1;
        }
        // P -> smem (tf32-rounded)
#pragma unroll
        for (int nt = 0; nt < 8; nt++) {
            *(float2*)&Ss[(qw + g) * ALD + nt * 8 + 2 * t4] =
                make_float2(f2tf(s[nt][0]), f2tf(s[nt][1]));
            *(float2*)&Ss[(qw + g + 8) * ALD + nt * 8 + 2 * t4] =
                make_float2(f2tf(s[nt][2]), f2tf(s[nt][3]));
        }
        __syncthreads();

        // O += P @ V
#pragma unroll
        for (int kk8 = 0; kk8 < 8; kk8++) {
            int kk = kk8 * 8;
            uint32_t a0 = __float_as_uint(Ss[(qw + g) * ALD + kk + t4]);
            uint32_t a1 = __float_as_uint(Ss[(qw + g + 8) * ALD + kk + t4]);
            uint32_t a2 = __float_as_uint(Ss[(qw + g) * ALD + kk + t4 + 4]);
            uint32_t a3 = __float_as_uint(Ss[(qw + g + 8) * ALD + kk + t4 + 4]);
#pragma unroll
            for (int nt = 0; nt < 8; nt++) {
                uint32_t b0 = __float_as_uint(Vc[(kk + t4) * ALD + nt * 8 + g]);
                uint32_t b1 = __float_as_uint(Vc[(kk + t4 + 4) * ALD + nt * 8 + g]);
                mma_tf32(o[nt][0], o[nt][1], o[nt][2], o[nt][3], a0, a1, a2, a3, b0, b1);
            }
        }
    }

    // epilogue
    float inv0 = 1.f / lr0, inv1 = 1.f / lr1;
    int row0 = q0 + qw + g, row1 = row0 + 8;
#pragma unroll
    for (int nt = 0; nt < 8; nt++) {
        int col = h * DD + nt * 8 + 2 * t4;
        *(float2*)&g_attn[((size_t)b * SSEQ + row0) * EE + col] =
            make_float2(o[nt][0] * inv0, o[nt][1] * inv0);
        *(float2*)&g_attn[((size_t)b * SSEQ + row1) * EE + col] =
            make_float2(o[nt][2] * inv1, o[nt][3] * inv1);
    }
}

// ---------------------------------------------------------------------------
extern "C" void kernel_launch(void* const* d_in, const int* in_sizes, int n_in,
                              void* d_out, int out_size) {
    const float* query = (const float*)d_in[0];
    const float* key   = (const float*)d_in[1];
    const float* value = (const float*)d_in[2];
    const int*   mask  = (const int*)d_in[3];
    const float* Wq = (const float*)d_in[4];
    const float* bq = (const float*)d_in[5];
    const float* Wk = (const float*)d_in[6];
    const float* bk = (const float*)d_in[7];
    const float* Wv = (const float*)d_in[8];
    const float* bv = (const float*)d_in[9];
    const float* Wo = (const float*)d_in[10];
    const float* bo = (const float*)d_in[11];
    float* out = (float*)d_out;

    dim3 qkv_grid(EE / 128, MMROWS / 128, 3);  // (8, 32, 3)
    gemm_qkv<<<qkv_grid, 256>>>(query, key, value, Wq, bq, Wk, bk, Wv, bv);

    const int smem = (4 * 64 * ALD + QTT * ALD) * (int)sizeof(float) + 2 * 64 * (int)sizeof(int);
    static bool attr_set = false;
    if (!attr_set) {
        cudaFuncSetAttribute(attn_tc, cudaFuncAttributeMaxDynamicSharedMemorySize, smem);
        attr_set = true;
    }
    attn_tc<<<dim3(SSEQ / QTT, BB * HH), 256, smem>>>(mask);

    gemm_out<<<dim3(EE / 128, MMROWS / 128), 256>>>(Wo, bo, out);
}

// round 6
// speedup vs baseline: 1.0828x; 1.0828x over previous
#include <cuda_runtime.h>
#include <math.h>
#include <stdint.h>

// Problem dims
#define BB 2
#define SSEQ 2048
#define EE 1024
#define HH 16
#define DD 64
#define MMROWS (BB * SSEQ)  // 4096

// Scratch (device globals: allocation-free)
__device__ float g_Q[BB * HH * SSEQ * DD];
__device__ float g_K[BB * HH * SSEQ * DD];
__device__ float g_V[BB * HH * DD * SSEQ];  // TRANSPOSED: [b,h,d,s]
__device__ float g_attn[BB * SSEQ * EE];

// ---------------------------------------------------------------------------
// helpers
// ---------------------------------------------------------------------------
__device__ __forceinline__ float f2tf(float x) {
    uint32_t r;
    asm("cvt.rna.tf32.f32 %0, %1;" : "=r"(r) : "f"(x));
    return __uint_as_float(r);
}

__device__ __forceinline__ void mma_tf32(float& c0, float& c1, float& c2, float& c3,
                                         uint32_t a0, uint32_t a1, uint32_t a2, uint32_t a3,
                                         uint32_t b0, uint32_t b1) {
    asm volatile(
        "mma.sync.aligned.m16n8k8.row.col.f32.tf32.tf32.f32 "
        "{%0,%1,%2,%3}, {%4,%5,%6,%7}, {%8,%9}, {%0,%1,%2,%3};\n"
        : "+f"(c0), "+f"(c1), "+f"(c2), "+f"(c3)
        : "r"(a0), "r"(a1), "r"(a2), "r"(a3), "r"(b0), "r"(b1));
}

__device__ __forceinline__ void cpa16(uint32_t dst, const void* src) {
    asm volatile("cp.async.cg.shared.global [%0], [%1], 16;\n" :: "r"(dst), "l"(src));
}
__device__ __forceinline__ void cpa_commit() {
    asm volatile("cp.async.commit_group;\n");
}
__device__ __forceinline__ void cpa_wait_all() {
    asm volatile("cp.async.wait_group 0;\n");
}

// ---------------------------------------------------------------------------
// Fused QKV GEMM (grid.z selects Q/K/V), RoPE fused for Q/K, V written
// TRANSPOSED [b,h,d,s]. Row-major smem [128][20], register double-buffered.
// ---------------------------------------------------------------------------
#define GPD 20

__global__ __launch_bounds__(256) void gemm_qkv(
    const float* __restrict__ q_in, const float* __restrict__ k_in,
    const float* __restrict__ v_in,
    const float* __restrict__ Wq, const float* __restrict__ bq,
    const float* __restrict__ Wk, const float* __restrict__ bk,
    const float* __restrict__ Wv, const float* __restrict__ bv) {
    const int z = blockIdx.z;
    const float* A = (z == 0) ? q_in : (z == 1) ? k_in : v_in;
    const float* W = (z == 0) ? Wq : (z == 1) ? Wk : Wv;
    const float* bias = (z == 0) ? bq : (z == 1) ? bk : bv;
    float* dst = (z == 0) ? g_Q : (z == 1) ? g_K : g_V;

    __shared__ __align__(16) float As[2][128][GPD];
    __shared__ __align__(16) float Bs[2][128][GPD];
    __shared__ float invf[32];

    const int tid = threadIdx.x;
    const int n0 = blockIdx.x * 128;
    const int m0 = blockIdx.y * 128;
    const int wid = tid >> 5;
    const int lane = tid & 31;
    const int g = lane >> 2;
    const int t4 = lane & 3;
    const int mw = (wid & 1) * 64;
    const int nw = (wid >> 1) * 32;

    const int sm = tid >> 2;
    const int skq = (tid & 3) * 4;

    if (tid < 32)
        invf[tid] = (float)exp(-(double)tid * (9.210340371976184 / 32.0));

    float acc[4][4][4];
#pragma unroll
    for (int mt = 0; mt < 4; mt++)
#pragma unroll
        for (int nt = 0; nt < 4; nt++)
#pragma unroll
            for (int qq = 0; qq < 4; qq++) acc[mt][nt][qq] = 0.f;

    const int nsteps = EE / 16;  // 64

    {
        float4 va0 = *(const float4*)&A[(size_t)(m0 + sm) * EE + skq];
        float4 va1 = *(const float4*)&A[(size_t)(m0 + sm + 64) * EE + skq];
        float4 vw0 = *(const float4*)&W[(size_t)(n0 + sm) * EE + skq];
        float4 vw1 = *(const float4*)&W[(size_t)(n0 + sm + 64) * EE + skq];
        *(float4*)&As[0][sm][skq]      = make_float4(f2tf(va0.x), f2tf(va0.y), f2tf(va0.z), f2tf(va0.w));
        *(float4*)&As[0][sm + 64][skq] = make_float4(f2tf(va1.x), f2tf(va1.y), f2tf(va1.z), f2tf(va1.w));
        *(float4*)&Bs[0][sm][skq]      = make_float4(f2tf(vw0.x), f2tf(vw0.y), f2tf(vw0.z), f2tf(vw0.w));
        *(float4*)&Bs[0][sm + 64][skq] = make_float4(f2tf(vw1.x), f2tf(vw1.y), f2tf(vw1.z), f2tf(vw1.w));
    }
    __syncthreads();

    for (int s = 0; s < nsteps; s++) {
        const int cur = s & 1;
        float4 va0, va1, vw0, vw1;
        const bool more = (s + 1 < nsteps);
        if (more) {
            int k0 = (s + 1) * 16;
            va0 = *(const float4*)&A[(size_t)(m0 + sm) * EE + k0 + skq];
            va1 = *(const float4*)&A[(size_t)(m0 + sm + 64) * EE + k0 + skq];
            vw0 = *(const float4*)&W[(size_t)(n0 + sm) * EE + k0 + skq];
            vw1 = *(const float4*)&W[(size_t)(n0 + sm + 64) * EE + k0 + skq];
        }

#pragma unroll
        for (int kk = 0; kk < 16; kk += 8) {
            uint32_t af[4][4];
#pragma unroll
            for (int mt = 0; mt < 4; mt++) {
                int m = mw + mt * 16 + g;
                af[mt][0] = __float_as_uint(As[cur][m][kk + t4]);
                af[mt][1] = __float_as_uint(As[cur][m + 8][kk + t4]);
                af[mt][2] = __float_as_uint(As[cur][m][kk + t4 + 4]);
                af[mt][3] = __float_as_uint(As[cur][m + 8][kk + t4 + 4]);
            }
            uint32_t bf[4][2];
#pragma unroll
            for (int nt = 0; nt < 4; nt++) {
                int n = nw + nt * 8 + g;
                bf[nt][0] = __float_as_uint(Bs[cur][n][kk + t4]);
                bf[nt][1] = __float_as_uint(Bs[cur][n][kk + t4 + 4]);
            }
#pragma unroll
            for (int mt = 0; mt < 4; mt++)
#pragma unroll
                for (int nt = 0; nt < 4; nt++)
                    mma_tf32(acc[mt][nt][0], acc[mt][nt][1], acc[mt][nt][2], acc[mt][nt][3],
                             af[mt][0], af[mt][1], af[mt][2], af[mt][3],
                             bf[nt][0], bf[nt][1]);
        }

        if (more) {
            const int nxt = cur ^ 1;
            *(float4*)&As[nxt][sm][skq]      = make_float4(f2tf(va0.x), f2tf(va0.y), f2tf(va0.z), f2tf(va0.w));
            *(float4*)&As[nxt][sm + 64][skq] = make_float4(f2tf(va1.x), f2tf(va1.y), f2tf(va1.z), f2tf(va1.w));
            *(float4*)&Bs[nxt][sm][skq]      = make_float4(f2tf(vw0.x), f2tf(vw0.y), f2tf(vw0.z), f2tf(vw0.w));
            *(float4*)&Bs[nxt][sm + 64][skq] = make_float4(f2tf(vw1.x), f2tf(vw1.y), f2tf(vw1.z), f2tf(vw1.w));
            __syncthreads();
        }
    }

    // Epilogue: fragment cols (gn, gn+1), gn even == RoPE pair (2p, 2p+1).
#pragma unroll
    for (int mt = 0; mt < 4; mt++) {
        int gm0 = m0 + mw + mt * 16 + g;
        int gm1 = gm0 + 8;
        int s0 = gm0 & (SSEQ - 1), s1 = gm1 & (SSEQ - 1);
        int bb0 = gm0 >> 11, bb1 = gm1 >> 11;
#pragma unroll
        for (int nt = 0; nt < 4; nt++) {
            int gn = n0 + nw + nt * 8 + 2 * t4;
            int h = gn >> 6, d0 = gn & 63;
            float bv0 = bias[gn], bv1 = bias[gn + 1];
            float e00 = acc[mt][nt][0] + bv0, e01 = acc[mt][nt][1] + bv1;
            float e10 = acc[mt][nt][2] + bv0, e11 = acc[mt][nt][3] + bv1;
            if (z < 2) {  // RoPE on Q, K
                float if0 = invf[d0 & 31], if1 = invf[(d0 + 1) & 31];
                float sa, ca, sb, cb;
                sincosf((float)s0 * if0, &sa, &ca);
                sincosf((float)s0 * if1, &sb, &cb);
                float y00 = e00 * ca - e01 * sa;
                float y01 = e01 * cb + e00 * sb;
                sincosf((float)s1 * if0, &sa, &ca);
                sincosf((float)s1 * if1, &sb, &cb);
                float y10 = e10 * ca - e11 * sa;
                float y11 = e11 * cb + e10 * sb;
                e00 = y00; e01 = y01; e10 = y10; e11 = y11;
            }
            e00 = f2tf(e00); e01 = f2tf(e01); e10 = f2tf(e10); e11 = f2tf(e11);
            if (z < 2) {
                *(float2*)&dst[(((size_t)(bb0 * HH + h)) * SSEQ + s0) * DD + d0] = make_float2(e00, e01);
                *(float2*)&dst[(((size_t)(bb1 * HH + h)) * SSEQ + s1) * DD + d0] = make_float2(e10, e11);
            } else {
                // V transposed: [b,h,d,s]
                size_t vb = ((size_t)(bb0 * HH + h)) * DD;
                dst[(vb + d0) * SSEQ + s0]     = e00;
                dst[(vb + d0 + 1) * SSEQ + s0] = e01;
                size_t vb1 = ((size_t)(bb1 * HH + h)) * DD;
                dst[(vb1 + d0) * SSEQ + s1]     = e10;
                dst[(vb1 + d0 + 1) * SSEQ + s1] = e11;
            }
        }
    }
}

// ---------------------------------------------------------------------------
// Output GEMM: out = g_attn @ Wo^T + bo
// ---------------------------------------------------------------------------
__global__ __launch_bounds__(256) void gemm_out(const float* __restrict__ W,
                                                const float* __restrict__ bias,
                                                float* __restrict__ Cout) {
    const float* A = g_attn;

    __shared__ __align__(16) float As[2][128][GPD];
    __shared__ __align__(16) float Bs[2][128][GPD];

    const int tid = threadIdx.x;
    const int n0 = blockIdx.x * 128;
    const int m0 = blockIdx.y * 128;
    const int wid = tid >> 5;
    const int lane = tid & 31;
    const int g = lane >> 2;
    const int t4 = lane & 3;
    const int mw = (wid & 1) * 64;
    const int nw = (wid >> 1) * 32;
    const int sm = tid >> 2;
    const int skq = (tid & 3) * 4;

    float acc[4][4][4];
#pragma unroll
    for (int mt = 0; mt < 4; mt++)
#pragma unroll
        for (int nt = 0; nt < 4; nt++)
#pragma unroll
            for (int qq = 0; qq < 4; qq++) acc[mt][nt][qq] = 0.f;

    const int nsteps = EE / 16;

    {
        float4 va0 = *(const float4*)&A[(size_t)(m0 + sm) * EE + skq];
        float4 va1 = *(const float4*)&A[(size_t)(m0 + sm + 64) * EE + skq];
        float4 vw0 = *(const float4*)&W[(size_t)(n0 + sm) * EE + skq];
        float4 vw1 = *(const float4*)&W[(size_t)(n0 + sm + 64) * EE + skq];
        *(float4*)&As[0][sm][skq]      = make_float4(f2tf(va0.x), f2tf(va0.y), f2tf(va0.z), f2tf(va0.w));
        *(float4*)&As[0][sm + 64][skq] = make_float4(f2tf(va1.x), f2tf(va1.y), f2tf(va1.z), f2tf(va1.w));
        *(float4*)&Bs[0][sm][skq]      = make_float4(f2tf(vw0.x), f2tf(vw0.y), f2tf(vw0.z), f2tf(vw0.w));
        *(float4*)&Bs[0][sm + 64][skq] = make_float4(f2tf(vw1.x), f2tf(vw1.y), f2tf(vw1.z), f2tf(vw1.w));
    }
    __syncthreads();

    for (int s = 0; s < nsteps; s++) {
        const int cur = s & 1;
        float4 va0, va1, vw0, vw1;
        const bool more = (s + 1 < nsteps);
        if (more) {
            int k0 = (s + 1) * 16;
            va0 = *(const float4*)&A[(size_t)(m0 + sm) * EE + k0 + skq];
            va1 = *(const float4*)&A[(size_t)(m0 + sm + 64) * EE + k0 + skq];
            vw0 = *(const float4*)&W[(size_t)(n0 + sm) * EE + k0 + skq];
            vw1 = *(const float4*)&W[(size_t)(n0 + sm + 64) * EE + k0 + skq];
        }

#pragma unroll
        for (int kk = 0; kk < 16; kk += 8) {
            uint32_t af[4][4];
#pragma unroll
            for (int mt = 0; mt < 4; mt++) {
                int m = mw + mt * 16 + g;
                af[mt][0] = __float_as_uint(As[cur][m][kk + t4]);
                af[mt][1] = __float_as_uint(As[cur][m + 8][kk + t4]);
                af[mt][2] = __float_as_uint(As[cur][m][kk + t4 + 4]);
                af[mt][3] = __float_as_uint(As[cur][m + 8][kk + t4 + 4]);
            }
            uint32_t bf[4][2];
#pragma unroll
            for (int nt = 0; nt < 4; nt++) {
                int n = nw + nt * 8 + g;
                bf[nt][0] = __float_as_uint(Bs[cur][n][kk + t4]);
                bf[nt][1] = __float_as_uint(Bs[cur][n][kk + t4 + 4]);
            }
#pragma unroll
            for (int mt = 0; mt < 4; mt++)
#pragma unroll
                for (int nt = 0; nt < 4; nt++)
                    mma_tf32(acc[mt][nt][0], acc[mt][nt][1], acc[mt][nt][2], acc[mt][nt][3],
                             af[mt][0], af[mt][1], af[mt][2], af[mt][3],
                             bf[nt][0], bf[nt][1]);
        }

        if (more) {
            const int nxt = cur ^ 1;
            *(float4*)&As[nxt][sm][skq]      = make_float4(f2tf(va0.x), f2tf(va0.y), f2tf(va0.z), f2tf(va0.w));
            *(float4*)&As[nxt][sm + 64][skq] = make_float4(f2tf(va1.x), f2tf(va1.y), f2tf(va1.z), f2tf(va1.w));
            *(float4*)&Bs[nxt][sm][skq]      = make_float4(f2tf(vw0.x), f2tf(vw0.y), f2tf(vw0.z), f2tf(vw0.w));
            *(float4*)&Bs[nxt][sm + 64][skq] = make_float4(f2tf(vw1.x), f2tf(vw1.y), f2tf(vw1.z), f2tf(vw1.w));
            __syncthreads();
        }
    }

#pragma unroll
    for (int mt = 0; mt < 4; mt++) {
        int gm0 = m0 + mw + mt * 16 + g;
        int gm1 = gm0 + 8;
#pragma unroll
        for (int nt = 0; nt < 4; nt++) {
            int gn = n0 + nw + nt * 8 + 2 * t4;
            float bv0 = bias[gn], bv1 = bias[gn + 1];
            *(float2*)&Cout[(size_t)gm0 * EE + gn] = make_float2(acc[mt][nt][0] + bv0, acc[mt][nt][1] + bv1);
            *(float2*)&Cout[(size_t)gm1 * EE + gn] = make_float2(acc[mt][nt][2] + bv0, acc[mt][nt][3] + bv1);
        }
    }
}

// ---------------------------------------------------------------------------
// Flash attention, tf32 mma, cp.async double-buffered K/V (V transposed
// [d][s] -> PV B-fragment loads now bank-conflict-free, same pattern as K).
// CTA = 256 thr (8 warps x 16 q-rows = 128 q-rows), K tile 64. stride 68.
// ---------------------------------------------------------------------------
#define ALD 68
#define QTT 128
#define NTILE (SSEQ / 64)  // 32

__global__ __launch_bounds__(256) void attn_tc(const int* __restrict__ mask) {
    extern __shared__ __align__(16) float smx[];
    float* Kb[2] = {smx, smx + 64 * ALD};
    float* Vb[2] = {smx + 2 * 64 * ALD, smx + 3 * 64 * ALD};  // [d][s_local]
    float* Ss = smx + 4 * 64 * ALD;                 // [128][68]
    int* msk = (int*)(smx + 4 * 64 * ALD + QTT * ALD);  // [2][64]

    const int tid = threadIdx.x;
    const int wid = tid >> 5;
    const int lane = tid & 31;
    const int g = lane >> 2;
    const int t4 = lane & 3;
    const int qw = wid * 16;

    const int bh = blockIdx.y;
    const int q0 = blockIdx.x * QTT;
    const int b = bh / HH;
    const int h = bh - b * HH;
    const size_t base = (size_t)bh * SSEQ * DD;     // Q/K layout [b,h,s,d]
    const size_t basev = (size_t)bh * DD * SSEQ;    // V layout [b,h,d,s]

    const uint32_t smem_u32 = (uint32_t)__cvta_generic_to_shared(smx);
    const uint32_t kb_u32[2] = {smem_u32, smem_u32 + 64 * ALD * 4};
    const uint32_t vb_u32[2] = {smem_u32 + 2 * 64 * ALD * 4, smem_u32 + 3 * 64 * ALD * 4};
    const uint32_t msk_u32 = smem_u32 + (4 * 64 * ALD + QTT * ALD) * 4;

    // Q fragments (loop-invariant, pre-rounded tf32)
    uint32_t aq[8][4];
    {
        const float* qr0 = &g_Q[base + (size_t)(q0 + qw + g) * DD];
        const float* qr1 = qr0 + 8 * DD;
#pragma unroll
        for (int kk8 = 0; kk8 < 8; kk8++) {
            aq[kk8][0] = __float_as_uint(qr0[kk8 * 8 + t4]);
            aq[kk8][1] = __float_as_uint(qr1[kk8 * 8 + t4]);
            aq[kk8][2] = __float_as_uint(qr0[kk8 * 8 + t4 + 4]);
            aq[kk8][3] = __float_as_uint(qr1[kk8 * 8 + t4 + 4]);
        }
    }

    float o[8][4];
#pragma unroll
    for (int nt = 0; nt < 8; nt++)
#pragma unroll
        for (int qq = 0; qq < 4; qq++) o[nt][qq] = 0.f;
    float mr0 = -INFINITY, mr1 = -INFINITY, lr0 = 0.f, lr1 = 0.f;

    // prefetch tile 0
    {
#pragma unroll
        for (int u = 0; u < 4; u++) {
            int n = tid + 256 * u;
            int r = n >> 4, c = (n & 15) * 4;
            cpa16(kb_u32[0] + (r * ALD + c) * 4, &g_K[base + (size_t)r * DD + c]);
            cpa16(vb_u32[0] + (r * ALD + c) * 4, &g_V[basev + (size_t)r * SSEQ + c]);
        }
        if (tid < 16) cpa16(msk_u32 + tid * 16, &mask[b * SSEQ + tid * 4]);
        cpa_commit();
    }

    for (int kt = 0; kt < NTILE; kt++) {
        cpa_wait_all();
        __syncthreads();

        const int cur = kt & 1;
        if (kt + 1 < NTILE) {
            const int k0 = (kt + 1) * 64;
            const int nb = cur ^ 1;
#pragma unroll
            for (int u = 0; u < 4; u++) {
                int n = tid + 256 * u;
                int r = n >> 4, c = (n & 15) * 4;
                cpa16(kb_u32[nb] + (r * ALD + c) * 4, &g_K[base + (size_t)(k0 + r) * DD + c]);
                cpa16(vb_u32[nb] + (r * ALD + c) * 4, &g_V[basev + (size_t)r * SSEQ + k0 + c]);
            }
            if (tid < 16) cpa16(msk_u32 + 256 * nb + tid * 16, &mask[b * SSEQ + k0 + tid * 4]);
            cpa_commit();
        }

        const float* Kc = Kb[cur];
        const float* Vc = Vb[cur];
        const int* mc = msk + 64 * cur;

        // S = Q @ K^T
        float s[8][4];
#pragma unroll
        for (int nt = 0; nt < 8; nt++)
#pragma unroll
            for (int qq = 0; qq < 4; qq++) s[nt][qq] = 0.f;
#pragma unroll
        for (int kk8 = 0; kk8 < 8; kk8++) {
            int kk = kk8 * 8;
#pragma unroll
            for (int nt = 0; nt < 8; nt++) {
                uint32_t b0 = __float_as_uint(Kc[(nt * 8 + g) * ALD + kk + t4]);
                uint32_t b1 = __float_as_uint(Kc[(nt * 8 + g) * ALD + kk + t4 + 4]);
                mma_tf32(s[nt][0], s[nt][1], s[nt][2], s[nt][3],
                         aq[kk8][0], aq[kk8][1], aq[kk8][2], aq[kk8][3], b0, b1);
            }
        }

        // scale + mask
#pragma unroll
        for (int nt = 0; nt < 8; nt++) {
            int mka = mc[nt * 8 + 2 * t4];
            int mkb = mc[nt * 8 + 2 * t4 + 1];
            s[nt][0] = mka ? s[nt][0] * 0.125f : -1e30f;
            s[nt][1] = mkb ? s[nt][1] * 0.125f : -1e30f;
            s[nt][2] = mka ? s[nt][2] * 0.125f : -1e30f;
            s[nt][3] = mkb ? s[nt][3] * 0.125f : -1e30f;
        }

        // online softmax (rows g / g+8; reduce over 4-lane group)
        float m0 = -INFINITY, m1 = -INFINITY;
#pragma unroll
        for (int nt = 0; nt < 8; nt++) {
            m0 = fmaxf(m0, fmaxf(s[nt][0], s[nt][1]));
            m1 = fmaxf(m1, fmaxf(s[nt][2], s[nt][3]));
        }
#pragma unroll
        for (int off = 1; off <= 2; off <<= 1) {
            m0 = fmaxf(m0, __shfl_xor_sync(0xffffffffu, m0, off));
            m1 = fmaxf(m1, __shfl_xor_sync(0xffffffffu, m1, off));
        }
        float mn0 = fmaxf(mr0, m0), mn1 = fmaxf(mr1, m1);
        float al0 = __expf(mr0 - mn0), al1 = __expf(mr1 - mn1);
        float ls0 = 0.f, ls1 = 0.f;
#pragma unroll
        for (int nt = 0; nt < 8; nt++) {
            s[nt][0] = __expf(s[nt][0] - mn0);
            s[nt][1] = __expf(s[nt][1] - mn0);
            s[nt][2] = __expf(s[nt][2] - mn1);
            s[nt][3] = __expf(s[nt][3] - mn1);
            ls0 += s[nt][0] + s[nt][1];
            ls1 += s[nt][2] + s[nt][3];
        }
#pragma unroll
        for (int off = 1; off <= 2; off <<= 1) {
            ls0 += __shfl_xor_sync(0xffffffffu, ls0, off);
            ls1 += __shfl_xor_sync(0xffffffffu, ls1, off);
        }
        mr0 = mn0; mr1 = mn1;
        lr0 = lr0 * al0 + ls0;
        lr1 = lr1 * al1 + ls1;
#pragma unroll
        for (int nt = 0; nt < 8; nt++) {
            o[nt][0] *= al0; o[nt][1] *= al0;
            o[nt][2] *= al1; o[nt][3] *= al1;
        }
        // P -> smem (tf32-rounded)
#pragma unroll
        for (int nt = 0; nt < 8; nt++) {
            *(float2*)&Ss[(qw + g) * ALD + nt * 8 + 2 * t4] =
                make_float2(f2tf(s[nt][0]), f2tf(s[nt][1]));
            *(float2*)&Ss[(qw + g + 8) * ALD + nt * 8 + 2 * t4] =
                make_float2(f2tf(s[nt][2]), f2tf(s[nt][3]));
        }
        __syncthreads();

        // O += P @ V  (V stored [d][s]: B-frag = Vc[n_d][k_s], conflict-free)
#pragma unroll
        for (int kk8 = 0; kk8 < 8; kk8++) {
            int kk = kk8 * 8;
            uint32_t a0 = __float_as_uint(Ss[(qw + g) * ALD + kk + t4]);
            uint32_t a1 = __float_as_uint(Ss[(qw + g + 8) * ALD + kk + t4]);
            uint32_t a2 = __float_as_uint(Ss[(qw + g) * ALD + kk + t4 + 4]);
            uint32_t a3 = __float_as_uint(Ss[(qw + g + 8) * ALD + kk + t4 + 4]);
#pragma unroll
            for (int nt = 0; nt < 8; nt++) {
                uint32_t b0 = __float_as_uint(Vc[(nt * 8 + g) * ALD + kk + t4]);
                uint32_t b1 = __float_as_uint(Vc[(nt * 8 + g) * ALD + kk + t4 + 4]);
                mma_tf32(o[nt][0], o[nt][1], o[nt][2], o[nt][3], a0, a1, a2, a3, b0, b1);
            }
        }
    }

    // epilogue
    float inv0 = 1.f / lr0, inv1 = 1.f / lr1;
    int row0 = q0 + qw + g, row1 = row0 + 8;
#pragma unroll
    for (int nt = 0; nt < 8; nt++) {
        int col = h * DD + nt * 8 + 2 * t4;
        *(float2*)&g_attn[((size_t)b * SSEQ + row0) * EE + col] =
            make_float2(o[nt][0] * inv0, o[nt][1] * inv0);
        *(float2*)&g_attn[((size_t)b * SSEQ + row1) * EE + col] =
            make_float2(o[nt][2] * inv1, o[nt][3] * inv1);
    }
}

// ---------------------------------------------------------------------------
extern "C" void kernel_launch(void* const* d_in, const int* in_sizes, int n_in,
                              void* d_out, int out_size) {
    const float* query = (const float*)d_in[0];
    const float* key   = (const float*)d_in[1];
    const float* value = (const float*)d_in[2];
    const int*   mask  = (const int*)d_in[3];
    const float* Wq = (const float*)d_in[4];
    const float* bq = (const float*)d_in[5];
    const float* Wk = (const float*)d_in[6];
    const float* bk = (const float*)d_in[7];
    const float* Wv = (const float*)d_in[8];
    const float* bv = (const float*)d_in[9];
    const float* Wo = (const float*)d_in[10];
    const float* bo = (const float*)d_in[11];
    float* out = (float*)d_out;

    dim3 qkv_grid(EE / 128, MMROWS / 128, 3);  // (8, 32, 3)
    gemm_qkv<<<qkv_grid, 256>>>(query, key, value, Wq, bq, Wk, bk, Wv, bv);

    const int smem = (4 * 64 * ALD + QTT * ALD) * (int)sizeof(float) + 2 * 64 * (int)sizeof(int);
    static bool attr_set = false;
    if (!attr_set) {
        cudaFuncSetAttribute(attn_tc, cudaFuncAttributeMaxDynamicSharedMemorySize, smem);
        attr_set = true;
    }
    attn_tc<<<dim3(SSEQ / QTT, BB * HH), 256, smem>>>(mask);

    gemm_out<<<dim3(EE / 128, MMROWS / 128), 256>>>(Wo, bo, out);
}